// round 2
// baseline (speedup 1.0000x reference)
#include <cuda_runtime.h>
#include <math_constants.h>

#define N_ROWS 8192
#define D      128
#define MARGIN 0.3f

#define BM 128
#define BN 128
#define BK 32
#define TSTRIDE 132            // BM + 4 pad, keeps 16B alignment of rows
#define NSPLIT 16
#define TILES_PER_SPLIT ((N_ROWS / BN) / NSPLIT)   // 4

// Scratch (no allocations allowed): normalized embeddings + per-row min/max
__device__ float    g_xn[N_ROWS * D];
__device__ unsigned g_rmin[N_ROWS];   // order-preserving encoded float
__device__ unsigned g_rmax[N_ROWS];

// ---- order-preserving float <-> uint encoding (works for negatives) ----
__device__ __forceinline__ unsigned enc_f(float f) {
    unsigned u = __float_as_uint(f);
    return (u & 0x80000000u) ? ~u : (u | 0x80000000u);
}
__device__ __forceinline__ float dec_f(unsigned e) {
    return (e & 0x80000000u) ? __uint_as_float(e & 0x7FFFFFFFu)
                             : __uint_as_float(~e);
}

// ---- packed fp32x2 helpers (full-rate fp32 pipe on Blackwell) ----
__device__ __forceinline__ unsigned long long pack_dup(float a) {
    unsigned long long r;
    asm("mov.b64 %0, {%1, %1};" : "=l"(r) : "r"(__float_as_uint(a)));
    return r;
}
__device__ __forceinline__ void fma2(unsigned long long &d,
                                     unsigned long long a,
                                     unsigned long long b) {
    asm("fma.rn.f32x2 %0, %1, %2, %0;" : "+l"(d) : "l"(a), "l"(b));
}
__device__ __forceinline__ float lo32(unsigned long long v) {
    return __uint_as_float((unsigned)v);
}
__device__ __forceinline__ float hi32(unsigned long long v) {
    return __uint_as_float((unsigned)(v >> 32));
}

// ============================================================================
// Kernel 1: init per-row min/max sentinels
// ============================================================================
__global__ void init_kernel() {
    int i = blockIdx.x * blockDim.x + threadIdx.x;
    if (i < N_ROWS) { g_rmin[i] = 0xFFFFFFFFu; g_rmax[i] = 0u; }
}

// ============================================================================
// Kernel 2: L2-normalize rows: xn[i] = x[i] / (||x[i]|| + 1e-12)
// one warp per row, lane loads float4 (32 lanes * 4 = 128 = D)
// ============================================================================
__global__ void normalize_kernel(const float* __restrict__ in) {
    int warp = (blockIdx.x * blockDim.x + threadIdx.x) >> 5;
    int lane = threadIdx.x & 31;
    if (warp >= N_ROWS) return;
    float4 v = reinterpret_cast<const float4*>(in + warp * D)[lane];
    float ss = v.x * v.x + v.y * v.y + v.z * v.z + v.w * v.w;
    #pragma unroll
    for (int o = 16; o; o >>= 1) ss += __shfl_xor_sync(0xffffffffu, ss, o);
    float s = 1.0f / (sqrtf(ss) + 1e-12f);
    float4 w = make_float4(v.x * s, v.y * s, v.z * s, v.w * s);
    reinterpret_cast<float4*>(g_xn + warp * D)[lane] = w;
}

// ============================================================================
// Kernel 3: fused similarity + masked row min/max
// grid = (NSPLIT, N_ROWS/BM); block = 256 threads (16x16), 8x8 micro-tile
// ============================================================================
__global__ __launch_bounds__(256, 2)
void sim_kernel(const int* __restrict__ labels) {
    __shared__ float    As[BK][TSTRIDE];   // As[k][row]
    __shared__ float    Bs[BK][TSTRIDE];   // Bs[k][col]
    __shared__ int      s_lab[BN];
    __shared__ unsigned s_min[BM];
    __shared__ unsigned s_max[BM];

    const int tid = threadIdx.x;
    const int tx = tid & 15;       // 16 threads over columns
    const int ty = tid >> 4;       // 16 threads over rows
    const int rowBase = blockIdx.y * BM;

    if (tid < BM) { s_min[tid] = 0xFFFFFFFFu; s_max[tid] = 0u; }

    int lr[8];
    #pragma unroll
    for (int m = 0; m < 8; m++) lr[m] = labels[rowBase + ty * 8 + m];

    // loader mapping: warp covers 32 distinct rows at one 4-float k group
    const int l_kg  = tid & 7;     // k group of 4
    const int l_row = tid >> 3;    // 0..31

    float rmin[8], rmax[8];
    #pragma unroll
    for (int m = 0; m < 8; m++) { rmin[m] = CUDART_INF_F; rmax[m] = -CUDART_INF_F; }

    for (int t = 0; t < TILES_PER_SPLIT; t++) {
        const int colBase = (blockIdx.x * TILES_PER_SPLIT + t) * BN;

        unsigned long long acc[8][4];
        #pragma unroll
        for (int m = 0; m < 8; m++)
            #pragma unroll
            for (int c = 0; c < 4; c++) acc[m][c] = 0ull;

        for (int kc = 0; kc < D / BK; kc++) {
            __syncthreads();
            #pragma unroll
            for (int r4 = 0; r4 < 4; r4++) {
                const int row = l_row + 32 * r4;
                float4 va = *reinterpret_cast<const float4*>(
                    g_xn + (rowBase + row) * D + kc * BK + l_kg * 4);
                As[l_kg * 4 + 0][row] = va.x;
                As[l_kg * 4 + 1][row] = va.y;
                As[l_kg * 4 + 2][row] = va.z;
                As[l_kg * 4 + 3][row] = va.w;
                float4 vb = *reinterpret_cast<const float4*>(
                    g_xn + (colBase + row) * D + kc * BK + l_kg * 4);
                Bs[l_kg * 4 + 0][row] = vb.x;
                Bs[l_kg * 4 + 1][row] = vb.y;
                Bs[l_kg * 4 + 2][row] = vb.z;
                Bs[l_kg * 4 + 3][row] = vb.w;
            }
            if (kc == 0 && tid < BN) s_lab[tid] = labels[colBase + tid];
            __syncthreads();

            #pragma unroll
            for (int k = 0; k < BK; k++) {
                float4 a0 = *reinterpret_cast<const float4*>(&As[k][ty * 8]);
                float4 a1 = *reinterpret_cast<const float4*>(&As[k][ty * 8 + 4]);
                ulonglong2 b0 = *reinterpret_cast<const ulonglong2*>(&Bs[k][tx * 8]);
                ulonglong2 b1 = *reinterpret_cast<const ulonglong2*>(&Bs[k][tx * 8 + 4]);
                unsigned long long bp0 = b0.x, bp1 = b0.y, bp2 = b1.x, bp3 = b1.y;
                float av[8] = {a0.x, a0.y, a0.z, a0.w, a1.x, a1.y, a1.z, a1.w};
                #pragma unroll
                for (int m = 0; m < 8; m++) {
                    unsigned long long ap = pack_dup(av[m]);
                    fma2(acc[m][0], ap, bp0);
                    fma2(acc[m][1], ap, bp1);
                    fma2(acc[m][2], ap, bp2);
                    fma2(acc[m][3], ap, bp3);
                }
            }
        }

        // epilogue: apply masks, fold into running row min/max
        #pragma unroll
        for (int m = 0; m < 8; m++) {
            const int gi = rowBase + ty * 8 + m;
            const int li = lr[m];
            float mn = rmin[m], mx = rmax[m];
            #pragma unroll
            for (int c = 0; c < 4; c++) {
                const int j0 = colBase + tx * 8 + 2 * c;
                const int j1 = j0 + 1;
                const float d0 = lo32(acc[m][c]);
                const float d1 = hi32(acc[m][c]);
                const bool same0 = (li == s_lab[tx * 8 + 2 * c]);
                const bool same1 = (li == s_lab[tx * 8 + 2 * c + 1]);
                // positive candidate: dist if is_pos else dist+2
                float p0 = (same0 && gi != j0) ? d0 : d0 + 2.0f;
                float p1 = (same1 && gi != j1) ? d1 : d1 + 2.0f;
                // negative candidate: dist-2 if same else dist
                float n0 = same0 ? d0 - 2.0f : d0;
                float n1 = same1 ? d1 - 2.0f : d1;
                mn = fminf(mn, fminf(p0, p1));
                mx = fmaxf(mx, fmaxf(n0, n1));
            }
            rmin[m] = mn; rmax[m] = mx;
        }
    }

    // block-level combine (16 threads share each row) via shared atomics
    __syncthreads();
    #pragma unroll
    for (int m = 0; m < 8; m++) {
        atomicMin(&s_min[ty * 8 + m], enc_f(rmin[m]));
        atomicMax(&s_max[ty * 8 + m], enc_f(rmax[m]));
    }
    __syncthreads();
    if (tid < BM) {
        atomicMin(&g_rmin[rowBase + tid], s_min[tid]);
        atomicMax(&g_rmax[rowBase + tid], s_max[tid]);
    }
}

// ============================================================================
// Kernel 4: final sum over rows: sum(dist_an + margin - dist_ap)
// ============================================================================
__global__ void final_kernel(float* __restrict__ out) {
    __shared__ float red[256];
    const int tid = threadIdx.x;
    float s = 0.0f;
    for (int r = tid; r < N_ROWS; r += 256)
        s += dec_f(g_rmax[r]) + MARGIN - dec_f(g_rmin[r]);
    red[tid] = s;
    __syncthreads();
    #pragma unroll
    for (int o = 128; o; o >>= 1) {
        if (tid < o) red[tid] += red[tid + o];
        __syncthreads();
    }
    if (tid == 0) out[0] = red[0];
}

// ============================================================================
extern "C" void kernel_launch(void* const* d_in, const int* in_sizes, int n_in,
                              void* d_out, int out_size) {
    const float* inputs = (const float*)d_in[0];
    const int*   labels = (const int*)d_in[1];
    float*       out    = (float*)d_out;

    init_kernel<<<(N_ROWS + 255) / 256, 256>>>();
    normalize_kernel<<<N_ROWS / 8, 256>>>(inputs);   // 8 warps per block
    dim3 grid(NSPLIT, N_ROWS / BM);
    sim_kernel<<<grid, 256>>>(labels);
    final_kernel<<<1, 256>>>(out);
}

// round 3
// speedup vs baseline: 1.0031x; 1.0031x over previous
#include <cuda_runtime.h>
#include <math_constants.h>

#define N_ROWS 8192
#define D      128
#define MARGIN 0.3f

#define BM 128
#define BN 128
#define BK 32
#define TSTRIDE 132            // BM + 4 pad, keeps 16B alignment of rows
#define NSPLIT 16
#define TILES_PER_SPLIT ((N_ROWS / BN) / NSPLIT)   // 4

// Scratch (no allocations allowed): normalized embeddings + per-row min/max
__device__ float    g_xn[N_ROWS * D];
__device__ unsigned g_rmin[N_ROWS];   // order-preserving encoded float
__device__ unsigned g_rmax[N_ROWS];

// ---- order-preserving float <-> uint encoding (works for negatives) ----
__device__ __forceinline__ unsigned enc_f(float f) {
    unsigned u = __float_as_uint(f);
    return (u & 0x80000000u) ? ~u : (u | 0x80000000u);
}
__device__ __forceinline__ float dec_f(unsigned e) {
    return (e & 0x80000000u) ? __uint_as_float(e & 0x7FFFFFFFu)
                             : __uint_as_float(~e);
}

// ---- packed fp32x2 helpers (full-rate fp32 pipe on Blackwell) ----
__device__ __forceinline__ unsigned long long pack_dup(float a) {
    unsigned long long r;
    asm("mov.b64 %0, {%1, %1};" : "=l"(r) : "r"(__float_as_uint(a)));
    return r;
}
__device__ __forceinline__ void fma2(unsigned long long &d,
                                     unsigned long long a,
                                     unsigned long long b) {
    asm("fma.rn.f32x2 %0, %1, %2, %0;" : "+l"(d) : "l"(a), "l"(b));
}
__device__ __forceinline__ float lo32(unsigned long long v) {
    return __uint_as_float((unsigned)v);
}
__device__ __forceinline__ float hi32(unsigned long long v) {
    return __uint_as_float((unsigned)(v >> 32));
}

// ============================================================================
// Kernel 1: init per-row min/max sentinels
// ============================================================================
__global__ void init_kernel() {
    int i = blockIdx.x * blockDim.x + threadIdx.x;
    if (i < N_ROWS) { g_rmin[i] = 0xFFFFFFFFu; g_rmax[i] = 0u; }
}

// ============================================================================
// Kernel 2: L2-normalize rows: xn[i] = x[i] / (||x[i]|| + 1e-12)
// one warp per row, lane loads float4 (32 lanes * 4 = 128 = D)
// ============================================================================
__global__ void normalize_kernel(const float* __restrict__ in) {
    int warp = (blockIdx.x * blockDim.x + threadIdx.x) >> 5;
    int lane = threadIdx.x & 31;
    if (warp >= N_ROWS) return;
    float4 v = reinterpret_cast<const float4*>(in + warp * D)[lane];
    float ss = v.x * v.x + v.y * v.y + v.z * v.z + v.w * v.w;
    #pragma unroll
    for (int o = 16; o; o >>= 1) ss += __shfl_xor_sync(0xffffffffu, ss, o);
    float s = 1.0f / (sqrtf(ss) + 1e-12f);
    float4 w = make_float4(v.x * s, v.y * s, v.z * s, v.w * s);
    reinterpret_cast<float4*>(g_xn + warp * D)[lane] = w;
}

// ============================================================================
// Kernel 3: fused similarity + masked row min/max
// grid = (NSPLIT, N_ROWS/BM); block = 256 threads (16x16), 8x8 micro-tile
// ============================================================================
__global__ __launch_bounds__(256, 2)
void sim_kernel(const int* __restrict__ labels) {
    __shared__ float    As[BK][TSTRIDE];   // As[k][row]
    __shared__ float    Bs[BK][TSTRIDE];   // Bs[k][col]
    __shared__ int      s_lab[BN];
    __shared__ unsigned s_min[BM];
    __shared__ unsigned s_max[BM];

    const int tid = threadIdx.x;
    const int tx = tid & 15;       // 16 threads over columns
    const int ty = tid >> 4;       // 16 threads over rows
    const int rowBase = blockIdx.y * BM;

    if (tid < BM) { s_min[tid] = 0xFFFFFFFFu; s_max[tid] = 0u; }

    int lr[8];
    #pragma unroll
    for (int m = 0; m < 8; m++) lr[m] = labels[rowBase + ty * 8 + m];

    // loader mapping: warp covers 32 distinct rows at one 4-float k group
    const int l_kg  = tid & 7;     // k group of 4
    const int l_row = tid >> 3;    // 0..31

    float rmin[8], rmax[8];
    #pragma unroll
    for (int m = 0; m < 8; m++) { rmin[m] = CUDART_INF_F; rmax[m] = -CUDART_INF_F; }

    for (int t = 0; t < TILES_PER_SPLIT; t++) {
        const int colBase = (blockIdx.x * TILES_PER_SPLIT + t) * BN;

        unsigned long long acc[8][4];
        #pragma unroll
        for (int m = 0; m < 8; m++)
            #pragma unroll
            for (int c = 0; c < 4; c++) acc[m][c] = 0ull;

        for (int kc = 0; kc < D / BK; kc++) {
            __syncthreads();
            #pragma unroll
            for (int r4 = 0; r4 < 4; r4++) {
                const int row = l_row + 32 * r4;
                float4 va = *reinterpret_cast<const float4*>(
                    g_xn + (rowBase + row) * D + kc * BK + l_kg * 4);
                As[l_kg * 4 + 0][row] = va.x;
                As[l_kg * 4 + 1][row] = va.y;
                As[l_kg * 4 + 2][row] = va.z;
                As[l_kg * 4 + 3][row] = va.w;
                float4 vb = *reinterpret_cast<const float4*>(
                    g_xn + (colBase + row) * D + kc * BK + l_kg * 4);
                Bs[l_kg * 4 + 0][row] = vb.x;
                Bs[l_kg * 4 + 1][row] = vb.y;
                Bs[l_kg * 4 + 2][row] = vb.z;
                Bs[l_kg * 4 + 3][row] = vb.w;
            }
            if (kc == 0 && tid < BN) s_lab[tid] = labels[colBase + tid];
            __syncthreads();

            #pragma unroll
            for (int k = 0; k < BK; k++) {
                float4 a0 = *reinterpret_cast<const float4*>(&As[k][ty * 8]);
                float4 a1 = *reinterpret_cast<const float4*>(&As[k][ty * 8 + 4]);
                ulonglong2 b0 = *reinterpret_cast<const ulonglong2*>(&Bs[k][tx * 8]);
                ulonglong2 b1 = *reinterpret_cast<const ulonglong2*>(&Bs[k][tx * 8 + 4]);
                unsigned long long bp0 = b0.x, bp1 = b0.y, bp2 = b1.x, bp3 = b1.y;
                float av[8] = {a0.x, a0.y, a0.z, a0.w, a1.x, a1.y, a1.z, a1.w};
                #pragma unroll
                for (int m = 0; m < 8; m++) {
                    unsigned long long ap = pack_dup(av[m]);
                    fma2(acc[m][0], ap, bp0);
                    fma2(acc[m][1], ap, bp1);
                    fma2(acc[m][2], ap, bp2);
                    fma2(acc[m][3], ap, bp3);
                }
            }
        }

        // epilogue: apply masks, fold into running row min/max
        #pragma unroll
        for (int m = 0; m < 8; m++) {
            const int gi = rowBase + ty * 8 + m;
            const int li = lr[m];
            float mn = rmin[m], mx = rmax[m];
            #pragma unroll
            for (int c = 0; c < 4; c++) {
                const int j0 = colBase + tx * 8 + 2 * c;
                const int j1 = j0 + 1;
                const float d0 = lo32(acc[m][c]);
                const float d1 = hi32(acc[m][c]);
                const bool same0 = (li == s_lab[tx * 8 + 2 * c]);
                const bool same1 = (li == s_lab[tx * 8 + 2 * c + 1]);
                // positive candidate: dist if is_pos else dist+2
                float p0 = (same0 && gi != j0) ? d0 : d0 + 2.0f;
                float p1 = (same1 && gi != j1) ? d1 : d1 + 2.0f;
                // negative candidate: dist-2 if same else dist
                float n0 = same0 ? d0 - 2.0f : d0;
                float n1 = same1 ? d1 - 2.0f : d1;
                mn = fminf(mn, fminf(p0, p1));
                mx = fmaxf(mx, fmaxf(n0, n1));
            }
            rmin[m] = mn; rmax[m] = mx;
        }
    }

    // block-level combine (16 threads share each row) via shared atomics
    __syncthreads();
    #pragma unroll
    for (int m = 0; m < 8; m++) {
        atomicMin(&s_min[ty * 8 + m], enc_f(rmin[m]));
        atomicMax(&s_max[ty * 8 + m], enc_f(rmax[m]));
    }
    __syncthreads();
    if (tid < BM) {
        atomicMin(&g_rmin[rowBase + tid], s_min[tid]);
        atomicMax(&g_rmax[rowBase + tid], s_max[tid]);
    }
}

// ============================================================================
// Kernel 4: final sum over rows: sum(dist_an + margin - dist_ap)
// ============================================================================
__global__ void final_kernel(float* __restrict__ out) {
    __shared__ float red[256];
    const int tid = threadIdx.x;
    float s = 0.0f;
    for (int r = tid; r < N_ROWS; r += 256)
        s += dec_f(g_rmax[r]) + MARGIN - dec_f(g_rmin[r]);
    red[tid] = s;
    __syncthreads();
    #pragma unroll
    for (int o = 128; o; o >>= 1) {
        if (tid < o) red[tid] += red[tid + o];
        __syncthreads();
    }
    if (tid == 0) out[0] = red[0];
}

// ============================================================================
extern "C" void kernel_launch(void* const* d_in, const int* in_sizes, int n_in,
                              void* d_out, int out_size) {
    const float* inputs = (const float*)d_in[0];
    const int*   labels = (const int*)d_in[1];
    float*       out    = (float*)d_out;

    init_kernel<<<(N_ROWS + 255) / 256, 256>>>();
    normalize_kernel<<<N_ROWS / 8, 256>>>(inputs);   // 8 warps per block
    dim3 grid(NSPLIT, N_ROWS / BM);
    sim_kernel<<<grid, 256>>>(labels);
    final_kernel<<<1, 256>>>(out);
}